// round 1
// baseline (speedup 1.0000x reference)
#include <cuda_runtime.h>
#include <cstddef>

// ---------------------------------------------------------------------------
// SAGEConv: gather+mean-agg -> concat -> Linear(1024->512)+ReLU -> BatchNorm
//           (batch stats) -> row L2 normalize
// Shapes: features[40000,512] f32, W[512,1024] f32, b/gamma/beta[512],
//         self_idx[20000], neigh_idx[20000,25] (int32 OR int64 — detected),
//         out[20000,512] f32
// ---------------------------------------------------------------------------

#define DD      512          // output feature dim
#define KK      1024         // concat dim (2*DD)
#define NMAX    20000        // N rows
#define MAXBLK  160          // ceil(NMAX/128)

// GEMM tiling
#define BM 128
#define BN 128
#define BKg 8
#define TM 8
#define TN 8

// ------------------------- device scratch (no mallocs) ---------------------
__device__ __align__(16) float g_A[(size_t)NMAX * KK];     // concat matrix  ~82 MB
__device__ __align__(16) float g_H[(size_t)NMAX * DD];     // post-ReLU      ~41 MB
__device__ float g_psum [MAXBLK * DD];
__device__ float g_psumsq[MAXBLK * DD];
__device__ __align__(16) float g_scale[DD];
__device__ __align__(16) float g_shift[DD];
__device__ int   g_idx_is64;

// ------------------------- f32x2 packed math helpers -----------------------
__device__ __forceinline__ unsigned long long pack2(float lo, float hi) {
    unsigned long long r;
    asm("mov.b64 %0, {%1, %2};" : "=l"(r) : "f"(lo), "f"(hi));
    return r;
}
__device__ __forceinline__ void unpack2(unsigned long long v, float& lo, float& hi) {
    asm("mov.b64 {%0, %1}, %2;" : "=f"(lo), "=f"(hi) : "l"(v));
}
__device__ __forceinline__ void fma2(unsigned long long& d,
                                     unsigned long long a, unsigned long long b) {
    asm("fma.rn.f32x2 %0, %1, %2, %0;" : "+l"(d) : "l"(a), "l"(b));
}

// ------------------------- index dtype detection ---------------------------
// If the index buffers are int64 (values < 2^31, non-negative), every odd
// 32-bit word is a zero high-word. For int32 random indices in [0,40000),
// the OR of ~N/2 values is nonzero with overwhelming probability.
__global__ void detect_idx_kernel(const unsigned int* __restrict__ p, int n) {
    __shared__ unsigned int red[256];
    unsigned int acc = 0;
    for (int i = threadIdx.x; i < n; i += blockDim.x)
        if (i & 1) acc |= p[i];
    red[threadIdx.x] = acc;
    __syncthreads();
    for (int s = 128; s > 0; s >>= 1) {
        if (threadIdx.x < s) red[threadIdx.x] |= red[threadIdx.x + s];
        __syncthreads();
    }
    if (threadIdx.x == 0) g_idx_is64 = (red[0] == 0u) ? 1 : 0;
}

__device__ __forceinline__ long long load_idx(const void* p, size_t i, int is64) {
    if (is64) return ((const long long*)p)[i];
    return (long long)((const int*)p)[i];
}

// ------------------------- kernel 1: gather + mean aggregate ---------------
// One block per output row. 128 threads; each owns one float4 column group.
__global__ __launch_bounds__(128)
void agg_kernel(const float4* __restrict__ feat4,
                const void* __restrict__ self_idx,
                const void* __restrict__ neigh_idx,
                int N, int S) {
    const int n = blockIdx.x;
    const int t = threadIdx.x;
    __shared__ long long sidx[40];   // S(<=32) neighbors + self at [S]
    const int is64 = g_idx_is64;
    if (t == 0) sidx[S] = load_idx(self_idx, n, is64);
    if (t < S)  sidx[t] = load_idx(neigh_idx, (size_t)n * S + t, is64);
    __syncthreads();

    float4* A4 = reinterpret_cast<float4*>(g_A);
    const long long si = sidx[S];
    A4[(size_t)n * 256 + t] = feat4[(size_t)si * 128 + t];

    float4 acc = make_float4(0.f, 0.f, 0.f, 0.f);
    for (int s = 0; s < S; ++s) {
        const long long id = sidx[s];
        float4 v = feat4[(size_t)id * 128 + t];
        acc.x += v.x; acc.y += v.y; acc.z += v.z; acc.w += v.w;
    }
    const float inv = 1.0f / (float)S;
    acc.x *= inv; acc.y *= inv; acc.z *= inv; acc.w *= inv;
    A4[(size_t)n * 256 + 128 + t] = acc;
}

// ------------------------- kernel 2: GEMM + bias + ReLU --------------------
// H[m,n] = relu( sum_k A[m,k] * W[n,k] + bias[n] )   (both K-major -> NT GEMM)
// 128x128 block tile, 8x8 per thread, f32x2 packed FMA accumulators.
__global__ __launch_bounds__(256, 2)
void gemm_relu_kernel(const float* __restrict__ Wt,
                      const float* __restrict__ bias, int M) {
    __shared__ float As[BKg][BM];
    __shared__ float Bs[BKg][BN];

    const int tid      = threadIdx.x;
    const int blockRow = blockIdx.y;
    const int blockCol = blockIdx.x;

    const int loadRow = tid >> 1;          // 0..127
    const int loadC4  = (tid & 1) << 2;    // 0 or 4

    const int threadRow = tid >> 4;        // 0..15
    const int threadCol = tid & 15;        // 0..15

    unsigned long long acc[TM][TN / 2];
    #pragma unroll
    for (int i = 0; i < TM; ++i)
        #pragma unroll
        for (int j = 0; j < TN / 2; ++j) acc[i][j] = 0ULL;

    const int gARow = blockRow * BM + loadRow;
    const bool aValid = (gARow < M);
    const float* Aptr = g_A + (size_t)gARow * KK + loadC4;
    const float* Bptr = Wt + (size_t)(blockCol * BN + loadRow) * KK + loadC4;

    float4 aReg = aValid ? *(const float4*)Aptr : make_float4(0.f, 0.f, 0.f, 0.f);
    float4 bReg = *(const float4*)Bptr;

    const int KT = KK / BKg;
    for (int kt = 0; kt < KT; ++kt) {
        As[loadC4 + 0][loadRow] = aReg.x;
        As[loadC4 + 1][loadRow] = aReg.y;
        As[loadC4 + 2][loadRow] = aReg.z;
        As[loadC4 + 3][loadRow] = aReg.w;
        Bs[loadC4 + 0][loadRow] = bReg.x;
        Bs[loadC4 + 1][loadRow] = bReg.y;
        Bs[loadC4 + 2][loadRow] = bReg.z;
        Bs[loadC4 + 3][loadRow] = bReg.w;
        __syncthreads();

        if (kt + 1 < KT) {   // prefetch next k-slab while computing
            const float* An = Aptr + (size_t)(kt + 1) * BKg;
            aReg = aValid ? *(const float4*)An : make_float4(0.f, 0.f, 0.f, 0.f);
            bReg = *(const float4*)(Bptr + (size_t)(kt + 1) * BKg);
        }

        #pragma unroll
        for (int k = 0; k < BKg; ++k) {
            unsigned long long bfrag[TN / 2];
            const unsigned long long* brow =
                (const unsigned long long*)&Bs[k][threadCol * TN];
            #pragma unroll
            for (int j = 0; j < TN / 2; ++j) bfrag[j] = brow[j];
            #pragma unroll
            for (int i = 0; i < TM; ++i) {
                float a = As[k][threadRow * TM + i];
                unsigned long long a2 = pack2(a, a);
                #pragma unroll
                for (int j = 0; j < TN / 2; ++j) fma2(acc[i][j], a2, bfrag[j]);
            }
        }
        __syncthreads();
    }

    // epilogue: bias + relu, store to g_H
    const int n0 = blockCol * BN + threadCol * TN;
    float bv[TN];
    #pragma unroll
    for (int j = 0; j < TN; ++j) bv[j] = bias[n0 + j];

    #pragma unroll
    for (int i = 0; i < TM; ++i) {
        const int m = blockRow * BM + threadRow * TM + i;
        if (m >= M) continue;
        float v[TN];
        #pragma unroll
        for (int j = 0; j < TN / 2; ++j) unpack2(acc[i][j], v[2 * j], v[2 * j + 1]);
        #pragma unroll
        for (int j = 0; j < TN; ++j) {
            v[j] += bv[j];
            v[j] = v[j] > 0.f ? v[j] : 0.f;
        }
        float* hrow = g_H + (size_t)m * DD + n0;
        *(float4*)(hrow + 0) = make_float4(v[0], v[1], v[2], v[3]);
        *(float4*)(hrow + 4) = make_float4(v[4], v[5], v[6], v[7]);
    }
}

// ------------------------- kernel 3: BN partial stats ----------------------
// Each block reduces 128 rows into per-column partial sum / sumsq (deterministic).
__global__ __launch_bounds__(256)
void stats_kernel(int M) {
    const int b = blockIdx.x;
    const int r0 = b * 128;
    const int t = threadIdx.x;                 // 0..255 -> cols t and t+256
    float s0 = 0.f, q0 = 0.f, s1 = 0.f, q1 = 0.f;
    const int rend = min(M - r0, 128);
    for (int r = 0; r < rend; ++r) {
        const float* row = g_H + (size_t)(r0 + r) * DD;
        float v = row[t];        s0 += v; q0 += v * v;
        float w = row[t + 256];  s1 += w; q1 += w * w;
    }
    g_psum  [b * DD + t]       = s0;
    g_psumsq[b * DD + t]       = q0;
    g_psum  [b * DD + t + 256] = s1;
    g_psumsq[b * DD + t + 256] = q1;
}

// finalize: reduce partials, fold BN affine into scale/shift
__global__ __launch_bounds__(DD)
void finalize_stats(const float* __restrict__ gamma,
                    const float* __restrict__ beta, int M, int nblk) {
    const int t = threadIdx.x;   // 0..511
    float s = 0.f, q = 0.f;
    for (int i = 0; i < nblk; ++i) {
        s += g_psum  [i * DD + t];
        q += g_psumsq[i * DD + t];
    }
    const float invM = 1.0f / (float)M;
    const float mean = s * invM;
    const float var  = q * invM - mean * mean;
    const float rstd = rsqrtf(var + 1e-5f);
    const float sc = rstd * gamma[t];
    g_scale[t] = sc;
    g_shift[t] = beta[t] - mean * sc;
}

// ------------------------- kernel 4: BN apply + row L2 normalize -----------
__global__ __launch_bounds__(128)
void bn_l2_kernel(float4* __restrict__ out4, int M) {
    const int n = blockIdx.x;
    const int t = threadIdx.x;   // 0..127
    const float4* H4  = reinterpret_cast<const float4*>(g_H);
    const float4* sc4 = reinterpret_cast<const float4*>(g_scale);
    const float4* sh4 = reinterpret_cast<const float4*>(g_shift);

    float4 h  = H4[(size_t)n * 128 + t];
    float4 sc = sc4[t];
    float4 sh = sh4[t];
    float4 y;
    y.x = h.x * sc.x + sh.x;
    y.y = h.y * sc.y + sh.y;
    y.z = h.z * sc.z + sh.z;
    y.w = h.w * sc.w + sh.w;

    float ss = y.x * y.x + y.y * y.y + y.z * y.z + y.w * y.w;
    #pragma unroll
    for (int o = 16; o > 0; o >>= 1)
        ss += __shfl_xor_sync(0xffffffffu, ss, o);

    __shared__ float ws[4];
    if ((t & 31) == 0) ws[t >> 5] = ss;
    __syncthreads();
    const float tot = ws[0] + ws[1] + ws[2] + ws[3];
    const float inv = 1.0f / (sqrtf(tot) + 1e-6f);

    y.x *= inv; y.y *= inv; y.z *= inv; y.w *= inv;
    out4[(size_t)n * 128 + t] = y;
}

// ------------------------- launcher ----------------------------------------
extern "C" void kernel_launch(void* const* d_in, const int* in_sizes, int n_in,
                              void* d_out, int out_size) {
    const float* features = (const float*)d_in[0];
    const float* W        = (const float*)d_in[1];
    const float* b        = (const float*)d_in[2];
    const float* gamma    = (const float*)d_in[3];
    const float* beta     = (const float*)d_in[4];
    const void*  self_idx = d_in[5];
    const void*  neigh_idx= d_in[6];

    const int N = in_sizes[5];
    const int S = in_sizes[6] / N;

    detect_idx_kernel<<<1, 256>>>((const unsigned int*)self_idx, N);

    agg_kernel<<<N, 128>>>((const float4*)features, self_idx, neigh_idx, N, S);

    dim3 ggrid(DD / BN, (N + BM - 1) / BM);
    gemm_relu_kernel<<<ggrid, 256>>>(W, b, N);

    const int nblk = (N + 127) / 128;
    stats_kernel<<<nblk, 256>>>(N);
    finalize_stats<<<1, DD>>>(gamma, beta, N, nblk);

    bn_l2_kernel<<<N, 128>>>((float4*)d_out, N);
}

// round 3
// speedup vs baseline: 2.0241x; 2.0241x over previous
#include <cuda_runtime.h>
#include <cuda_bf16.h>
#include <cstdint>
#include <cstddef>

// ---------------------------------------------------------------------------
// SAGEConv: gather+mean-agg -> concat -> Linear(1024->512)+ReLU -> BatchNorm
//           -> row L2 normalize.
// GEMM: warp-level mma.sync bf16 (hi/lo split, fp32 accum, 3 passes)
// ---------------------------------------------------------------------------

#define DD      512
#define KK      1024
#define NMAX    20000
#define NPAD    20096           // 157 * 128
#define MAXBLK  640

// ------------------------- device scratch (no mallocs) ---------------------
__device__ __align__(16) __nv_bfloat16 g_Ahi[(size_t)NPAD * KK];
__device__ __align__(16) __nv_bfloat16 g_Alo[(size_t)NPAD * KK];
__device__ __align__(16) __nv_bfloat16 g_Whi[(size_t)DD * KK];
__device__ __align__(16) __nv_bfloat16 g_Wlo[(size_t)DD * KK];
__device__ __align__(16) float g_H[(size_t)NMAX * DD];
__device__ float g_psum  [MAXBLK * DD];
__device__ float g_psumsq[MAXBLK * DD];
__device__ __align__(16) float g_scale[DD];
__device__ __align__(16) float g_shift[DD];
__device__ int   g_idx_is64;

// ------------------------- helpers -----------------------------------------
__device__ __forceinline__ uint32_t smem_u32(const void* p) {
    uint32_t a;
    asm("{ .reg .u64 t; cvta.to.shared.u64 t, %1; cvt.u32.u64 %0, t; }"
        : "=r"(a) : "l"(p));
    return a;
}
__device__ __forceinline__ void cpasync16(uint32_t dst, const void* src) {
    asm volatile("cp.async.cg.shared.global [%0], [%1], 16;"
                 :: "r"(dst), "l"(src) : "memory");
}
__device__ __forceinline__ void cp_commit() {
    asm volatile("cp.async.commit_group;" ::: "memory");
}
__device__ __forceinline__ void ldsm4(uint32_t& r0, uint32_t& r1,
                                      uint32_t& r2, uint32_t& r3, uint32_t a) {
    asm volatile("ldmatrix.sync.aligned.m8n8.x4.shared.b16 {%0,%1,%2,%3}, [%4];"
                 : "=r"(r0), "=r"(r1), "=r"(r2), "=r"(r3) : "r"(a));
}
__device__ __forceinline__ void mma16816(float* d, const uint32_t* a,
                                         const uint32_t* b) {
    asm volatile(
        "mma.sync.aligned.m16n8k16.row.col.f32.bf16.bf16.f32 "
        "{%0,%1,%2,%3}, {%4,%5,%6,%7}, {%8,%9}, {%0,%1,%2,%3};"
        : "+f"(d[0]), "+f"(d[1]), "+f"(d[2]), "+f"(d[3])
        : "r"(a[0]), "r"(a[1]), "r"(a[2]), "r"(a[3]), "r"(b[0]), "r"(b[1]));
}

// bf16 hi/lo split of two floats, packed as bf16x2 words (x0 in low half)
__device__ __forceinline__ void split2(float x0, float x1, uint32_t& hi2, uint32_t& lo2) {
    float h0 = __bfloat162float(__float2bfloat16_rn(x0));
    float h1 = __bfloat162float(__float2bfloat16_rn(x1));
    float l0 = x0 - h0, l1 = x1 - h1;
    asm("cvt.rn.bf16x2.f32 %0, %1, %2;" : "=r"(hi2) : "f"(h1), "f"(h0));
    asm("cvt.rn.bf16x2.f32 %0, %1, %2;" : "=r"(lo2) : "f"(l1), "f"(l0));
}

// ------------------------- index dtype detection ---------------------------
__global__ void detect_idx_kernel(const unsigned int* __restrict__ p, int n) {
    __shared__ unsigned int red[256];
    unsigned int acc = 0;
    for (int i = threadIdx.x; i < n; i += blockDim.x)
        if (i & 1) acc |= p[i];
    red[threadIdx.x] = acc;
    __syncthreads();
    for (int s = 128; s > 0; s >>= 1) {
        if (threadIdx.x < s) red[threadIdx.x] |= red[threadIdx.x + s];
        __syncthreads();
    }
    if (threadIdx.x == 0) g_idx_is64 = (red[0] == 0u) ? 1 : 0;
}
__device__ __forceinline__ long long load_idx(const void* p, size_t i, int is64) {
    if (is64) return ((const long long*)p)[i];
    return (long long)((const int*)p)[i];
}

// ------------------------- kernel 1: gather + mean agg -> bf16 hi/lo -------
__global__ __launch_bounds__(128)
void agg_kernel(const float4* __restrict__ feat4,
                const void* __restrict__ self_idx,
                const void* __restrict__ neigh_idx,
                int N, int S) {
    const int n = blockIdx.x;
    const int t = threadIdx.x;
    __shared__ long long sidx[40];
    const int is64 = g_idx_is64;
    if (t == 0) sidx[S] = load_idx(self_idx, n, is64);
    if (t < S)  sidx[t] = load_idx(neigh_idx, (size_t)n * S + t, is64);
    __syncthreads();

    uint2* Ah = reinterpret_cast<uint2*>(g_Ahi);
    uint2* Al = reinterpret_cast<uint2*>(g_Alo);

    {   // self half
        float4 v = feat4[(size_t)sidx[S] * 128 + t];
        uint2 hi, lo;
        split2(v.x, v.y, hi.x, lo.x);
        split2(v.z, v.w, hi.y, lo.y);
        Ah[(size_t)n * 256 + t] = hi;
        Al[(size_t)n * 256 + t] = lo;
    }
    float4 acc = make_float4(0.f, 0.f, 0.f, 0.f);
    for (int s = 0; s < S; ++s) {
        float4 v = feat4[(size_t)sidx[s] * 128 + t];
        acc.x += v.x; acc.y += v.y; acc.z += v.z; acc.w += v.w;
    }
    const float inv = 1.0f / (float)S;
    acc.x *= inv; acc.y *= inv; acc.z *= inv; acc.w *= inv;
    uint2 hi, lo;
    split2(acc.x, acc.y, hi.x, lo.x);
    split2(acc.z, acc.w, hi.y, lo.y);
    Ah[(size_t)n * 256 + 128 + t] = hi;
    Al[(size_t)n * 256 + 128 + t] = lo;
}

// ------------------------- kernel 1b: split W to bf16 hi/lo ----------------
__global__ __launch_bounds__(256)
void wconv_kernel(const float* __restrict__ W) {
    const int i = blockIdx.x * 256 + threadIdx.x;
    const float4 v = *(const float4*)(W + (size_t)i * 4);
    uint2 hi, lo;
    split2(v.x, v.y, hi.x, lo.x);
    split2(v.z, v.w, hi.y, lo.y);
    ((uint2*)g_Whi)[i] = hi;
    ((uint2*)g_Wlo)[i] = lo;
}

// ------------------------- kernel 2: HMMA GEMM + bias + ReLU ---------------
// H[128x128 tile] = A[128,1024] * W[128-slice,1024]^T, 3-pass hi/lo.
// smem stage: 4 variants (Ahi,Alo,Bhi,Blo) of [128 rows][32 k] bf16,
// row stride padded to 40 halfs (80B) -> conflict-free ldmatrix.
#define SASTRIDE 80                       // bytes per smem row
#define VARB     10240                    // 128*80 bytes per variant
#define STAGEB   (4 * VARB)               // 40960
#define NSTAGE   3
#define HDRB     1024
#define GEMM_SMEM (HDRB + NSTAGE * STAGEB)

__global__ __launch_bounds__(256)
void gemm_tc_kernel(const float* __restrict__ bias, int M) {
    extern __shared__ char smem[];
    const uint32_t sb = smem_u32(smem);
    const int tid  = threadIdx.x;
    const int wid  = tid >> 5;
    const int lane = tid & 31;
    const int wm   = wid >> 2;            // 0..1  (64 rows each)
    const int wn   = wid & 3;             // 0..3  (32 cols each)
    const int m0 = blockIdx.y * 128;
    const int n0 = blockIdx.x * 128;

    float* bsm = (float*)smem;            // bias cache [128]
    if (tid < 128) bsm[tid] = bias[n0 + tid];

    // per-lane ldmatrix offsets (bytes)
    const uint32_t aOff = (uint32_t)((lane & 15) * SASTRIDE + (lane >> 4) * 16);
    const uint32_t bOff = (uint32_t)(((lane & 7) + ((lane >> 4) << 3)) * SASTRIDE
                                     + (((lane >> 3) & 1) << 4));

    // chunk loader: 32 k per chunk, 4 variants
    const char* pAhi = (const char*)g_Ahi;
    const char* pAlo = (const char*)g_Alo;
    const char* pWhi = (const char*)g_Whi;
    const char* pWlo = (const char*)g_Wlo;

    auto load_chunk = [&](int stage, int kc) {
        const uint32_t base = sb + HDRB + stage * STAGEB;
        #pragma unroll
        for (int i = 0; i < 2; ++i) {
            const int idx = tid + (i << 8);
            const int r = idx >> 2, c = idx & 3;
            const uint32_t dst = base + (uint32_t)(r * SASTRIDE + c * 16);
            const size_t sa = ((size_t)(m0 + r) << 11) + (size_t)(kc * 64 + c * 16);
            const size_t sbo = ((size_t)(n0 + r) << 11) + (size_t)(kc * 64 + c * 16);
            cpasync16(dst,            pAhi + sa);
            cpasync16(dst + VARB,     pAlo + sa);
            cpasync16(dst + 2 * VARB, pWhi + sbo);
            cpasync16(dst + 3 * VARB, pWlo + sbo);
        }
        cp_commit();
    };

    float acc[4][4][4];
    #pragma unroll
    for (int i = 0; i < 4; ++i)
        #pragma unroll
        for (int j = 0; j < 4; ++j)
            #pragma unroll
            for (int q = 0; q < 4; ++q) acc[i][j][q] = 0.f;

    load_chunk(0, 0);
    load_chunk(1, 1);

    const int NKC = KK / 32;              // 32 chunks
    for (int kc = 0; kc < NKC; ++kc) {
        if (kc == NKC - 1) asm volatile("cp.async.wait_group 0;" ::: "memory");
        else               asm volatile("cp.async.wait_group 1;" ::: "memory");
        __syncthreads();

        if (kc + 2 < NKC) load_chunk((kc + 2) % NSTAGE, kc + 2);

        const uint32_t st = sb + HDRB + (kc % NSTAGE) * STAGEB;
        const uint32_t bufAhi = st;
        const uint32_t bufAlo = st + VARB;
        const uint32_t bufBhi = st + 2 * VARB;
        const uint32_t bufBlo = st + 3 * VARB;

        #pragma unroll
        for (int k16 = 0; k16 < 2; ++k16) {
            const uint32_t kb = (uint32_t)(k16 * 32);   // 16 halfs = 32 bytes
            uint32_t ah[4][4], al[4][4], bh[2][4], bl[2][4];
            #pragma unroll
            for (int im = 0; im < 4; ++im) {
                const uint32_t ro = (uint32_t)((wm * 64 + im * 16) * SASTRIDE) + kb;
                ldsm4(ah[im][0], ah[im][1], ah[im][2], ah[im][3], bufAhi + ro + aOff);
                ldsm4(al[im][0], al[im][1], al[im][2], al[im][3], bufAlo + ro + aOff);
            }
            #pragma unroll
            for (int j2 = 0; j2 < 2; ++j2) {
                const uint32_t ro = (uint32_t)((wn * 32 + j2 * 16) * SASTRIDE) + kb;
                ldsm4(bh[j2][0], bh[j2][1], bh[j2][2], bh[j2][3], bufBhi + ro + bOff);
                ldsm4(bl[j2][0], bl[j2][1], bl[j2][2], bl[j2][3], bufBlo + ro + bOff);
            }
            #pragma unroll
            for (int im = 0; im < 4; ++im)
                #pragma unroll
                for (int jn = 0; jn < 4; ++jn) {
                    const uint32_t* ph = &bh[jn >> 1][(jn & 1) * 2];
                    const uint32_t* pl = &bl[jn >> 1][(jn & 1) * 2];
                    mma16816(acc[im][jn], ah[im], ph);   // hi*hi
                    mma16816(acc[im][jn], ah[im], pl);   // hi*lo
                    mma16816(acc[im][jn], al[im], ph);   // lo*hi
                }
        }
        __syncthreads();
    }

    // epilogue: bias + relu -> g_H
    const int g    = lane >> 2;
    const int tq   = lane & 3;
    #pragma unroll
    for (int im = 0; im < 4; ++im) {
        const int row0 = m0 + wm * 64 + im * 16 + g;
        #pragma unroll
        for (int jn = 0; jn < 4; ++jn) {
            const int colL = wn * 32 + jn * 8 + tq * 2;   // within 128-tile
            const float b0 = bsm[colL], b1 = bsm[colL + 1];
            float v0 = acc[im][jn][0] + b0;
            float v1 = acc[im][jn][1] + b1;
            float v2 = acc[im][jn][2] + b0;
            float v3 = acc[im][jn][3] + b1;
            v0 = v0 > 0.f ? v0 : 0.f;
            v1 = v1 > 0.f ? v1 : 0.f;
            v2 = v2 > 0.f ? v2 : 0.f;
            v3 = v3 > 0.f ? v3 : 0.f;
            const int col = n0 + colL;
            if (row0 < M)
                *(float2*)(g_H + (size_t)row0 * DD + col) = make_float2(v0, v1);
            if (row0 + 8 < M)
                *(float2*)(g_H + (size_t)(row0 + 8) * DD + col) = make_float2(v2, v3);
        }
    }
}

// ------------------------- kernel 3: BN partial stats ----------------------
__global__ __launch_bounds__(256)
void stats_kernel(int M) {
    const int b = blockIdx.x;
    const int r0 = b * 32;
    const int t = threadIdx.x;
    float s0 = 0.f, q0 = 0.f, s1 = 0.f, q1 = 0.f;
    const int rend = min(M - r0, 32);
    for (int r = 0; r < rend; ++r) {
        const float* row = g_H + (size_t)(r0 + r) * DD;
        float v = row[t];        s0 += v; q0 += v * v;
        float w = row[t + 256];  s1 += w; q1 += w * w;
    }
    g_psum  [b * DD + t]       = s0;
    g_psumsq[b * DD + t]       = q0;
    g_psum  [b * DD + t + 256] = s1;
    g_psumsq[b * DD + t + 256] = q1;
}

__global__ __launch_bounds__(256)
void finalize_stats(const float* __restrict__ gamma,
                    const float* __restrict__ beta, int M, int nblk) {
    const int col  = blockIdx.x * 8 + (threadIdx.x >> 5);
    const int lane = threadIdx.x & 31;
    float s = 0.f, q = 0.f;
    for (int i = lane; i < nblk; i += 32) {
        s += g_psum  [i * DD + col];
        q += g_psumsq[i * DD + col];
    }
    #pragma unroll
    for (int o = 16; o > 0; o >>= 1) {
        s += __shfl_xor_sync(0xffffffffu, s, o);
        q += __shfl_xor_sync(0xffffffffu, q, o);
    }
    if (lane == 0) {
        const float invM = 1.0f / (float)M;
        const float mean = s * invM;
        const float var  = q * invM - mean * mean;
        const float rstd = rsqrtf(var + 1e-5f);
        const float sc = rstd * gamma[col];
        g_scale[col] = sc;
        g_shift[col] = beta[col] - mean * sc;
    }
}

// ------------------------- kernel 4: BN apply + row L2 normalize -----------
__global__ __launch_bounds__(128)
void bn_l2_kernel(float4* __restrict__ out4, int M) {
    const int n = blockIdx.x;
    const int t = threadIdx.x;
    const float4* H4  = reinterpret_cast<const float4*>(g_H);
    const float4* sc4 = reinterpret_cast<const float4*>(g_scale);
    const float4* sh4 = reinterpret_cast<const float4*>(g_shift);

    float4 h  = H4[(size_t)n * 128 + t];
    float4 sc = sc4[t];
    float4 sh = sh4[t];
    float4 y;
    y.x = h.x * sc.x + sh.x;
    y.y = h.y * sc.y + sh.y;
    y.z = h.z * sc.z + sh.z;
    y.w = h.w * sc.w + sh.w;

    float ss = y.x * y.x + y.y * y.y + y.z * y.z + y.w * y.w;
    #pragma unroll
    for (int o = 16; o > 0; o >>= 1)
        ss += __shfl_xor_sync(0xffffffffu, ss, o);

    __shared__ float ws[4];
    if ((t & 31) == 0) ws[t >> 5] = ss;
    __syncthreads();
    const float tot = ws[0] + ws[1] + ws[2] + ws[3];
    const float inv = 1.0f / (sqrtf(tot) + 1e-6f);

    y.x *= inv; y.y *= inv; y.z *= inv; y.w *= inv;
    out4[(size_t)n * 128 + t] = y;
}

// ------------------------- launcher ----------------------------------------
extern "C" void kernel_launch(void* const* d_in, const int* in_sizes, int n_in,
                              void* d_out, int out_size) {
    const float* features = (const float*)d_in[0];
    const float* W        = (const float*)d_in[1];
    const float* b        = (const float*)d_in[2];
    const float* gamma    = (const float*)d_in[3];
    const float* beta     = (const float*)d_in[4];
    const void*  self_idx = d_in[5];
    const void*  neigh_idx= d_in[6];

    const int N = in_sizes[5];
    const int S = in_sizes[6] / N;

    cudaFuncSetAttribute(gemm_tc_kernel,
                         cudaFuncAttributeMaxDynamicSharedMemorySize, GEMM_SMEM);

    detect_idx_kernel<<<1, 256>>>((const unsigned int*)self_idx, N);

    agg_kernel<<<N, 128>>>((const float4*)features, self_idx, neigh_idx, N, S);
    wconv_kernel<<<(DD * KK / 4) / 256, 256>>>(W);

    dim3 ggrid(DD / 128, (N + 127) / 128);
    gemm_tc_kernel<<<ggrid, 256, GEMM_SMEM>>>(b, N);

    const int nblk = (N + 31) / 32;
    stats_kernel<<<nblk, 256>>>(N);
    finalize_stats<<<64, 256>>>(gamma, beta, N, nblk);

    bn_l2_kernel<<<N, 128>>>((float4*)d_out, N);
}

// round 4
// speedup vs baseline: 2.1443x; 1.0594x over previous
#include <cuda_runtime.h>
#include <cuda_bf16.h>
#include <cstdint>
#include <cstddef>

// ---------------------------------------------------------------------------
// SAGEConv: gather+mean-agg -> concat -> Linear(1024->512)+ReLU -> BatchNorm
//           -> row L2 normalize.
// GEMM: warp-level mma.sync bf16 (hi/lo split, fp32 accum, 3 passes)
// R4: 2-stage pipeline, 2 CTAs/SM (occupancy was the GEMM limiter)
// ---------------------------------------------------------------------------

#define DD      512
#define KK      1024
#define NMAX    20000
#define NPAD    20096           // 157 * 128
#define MAXBLK  640

// ------------------------- device scratch (no mallocs) ---------------------
__device__ __align__(16) __nv_bfloat16 g_Ahi[(size_t)NPAD * KK];
__device__ __align__(16) __nv_bfloat16 g_Alo[(size_t)NPAD * KK];
__device__ __align__(16) __nv_bfloat16 g_Whi[(size_t)DD * KK];
__device__ __align__(16) __nv_bfloat16 g_Wlo[(size_t)DD * KK];
__device__ __align__(16) float g_H[(size_t)NMAX * DD];
__device__ float g_psum  [MAXBLK * DD];
__device__ float g_psumsq[MAXBLK * DD];
__device__ __align__(16) float g_scale[DD];
__device__ __align__(16) float g_shift[DD];
__device__ int   g_idx_is64;

// ------------------------- helpers -----------------------------------------
__device__ __forceinline__ uint32_t smem_u32(const void* p) {
    uint32_t a;
    asm("{ .reg .u64 t; cvta.to.shared.u64 t, %1; cvt.u32.u64 %0, t; }"
        : "=r"(a) : "l"(p));
    return a;
}
__device__ __forceinline__ void cpasync16(uint32_t dst, const void* src) {
    asm volatile("cp.async.cg.shared.global [%0], [%1], 16;"
                 :: "r"(dst), "l"(src) : "memory");
}
__device__ __forceinline__ void cp_commit() {
    asm volatile("cp.async.commit_group;" ::: "memory");
}
__device__ __forceinline__ void ldsm4(uint32_t& r0, uint32_t& r1,
                                      uint32_t& r2, uint32_t& r3, uint32_t a) {
    asm volatile("ldmatrix.sync.aligned.m8n8.x4.shared.b16 {%0,%1,%2,%3}, [%4];"
                 : "=r"(r0), "=r"(r1), "=r"(r2), "=r"(r3) : "r"(a));
}
__device__ __forceinline__ void mma16816(float* d, const uint32_t* a,
                                         const uint32_t* b) {
    asm volatile(
        "mma.sync.aligned.m16n8k16.row.col.f32.bf16.bf16.f32 "
        "{%0,%1,%2,%3}, {%4,%5,%6,%7}, {%8,%9}, {%0,%1,%2,%3};"
        : "+f"(d[0]), "+f"(d[1]), "+f"(d[2]), "+f"(d[3])
        : "r"(a[0]), "r"(a[1]), "r"(a[2]), "r"(a[3]), "r"(b[0]), "r"(b[1]));
}

// bf16 hi/lo split of two floats, packed as bf16x2 words (x0 in low half)
__device__ __forceinline__ void split2(float x0, float x1, uint32_t& hi2, uint32_t& lo2) {
    float h0 = __bfloat162float(__float2bfloat16_rn(x0));
    float h1 = __bfloat162float(__float2bfloat16_rn(x1));
    float l0 = x0 - h0, l1 = x1 - h1;
    asm("cvt.rn.bf16x2.f32 %0, %1, %2;" : "=r"(hi2) : "f"(h1), "f"(h0));
    asm("cvt.rn.bf16x2.f32 %0, %1, %2;" : "=r"(lo2) : "f"(l1), "f"(l0));
}

// ------------------------- index dtype detection ---------------------------
__global__ void detect_idx_kernel(const unsigned int* __restrict__ p, int n) {
    __shared__ unsigned int red[256];
    unsigned int acc = 0;
    for (int i = threadIdx.x; i < n; i += blockDim.x)
        if (i & 1) acc |= p[i];
    red[threadIdx.x] = acc;
    __syncthreads();
    for (int s = 128; s > 0; s >>= 1) {
        if (threadIdx.x < s) red[threadIdx.x] |= red[threadIdx.x + s];
        __syncthreads();
    }
    if (threadIdx.x == 0) g_idx_is64 = (red[0] == 0u) ? 1 : 0;
}
__device__ __forceinline__ long long load_idx(const void* p, size_t i, int is64) {
    if (is64) return ((const long long*)p)[i];
    return (long long)((const int*)p)[i];
}

// ------------------------- kernel 1: gather + mean agg -> bf16 hi/lo -------
__global__ __launch_bounds__(128)
void agg_kernel(const float4* __restrict__ feat4,
                const void* __restrict__ self_idx,
                const void* __restrict__ neigh_idx,
                int N, int S) {
    const int n = blockIdx.x;
    const int t = threadIdx.x;
    __shared__ long long sidx[40];
    const int is64 = g_idx_is64;
    if (t == 0) sidx[S] = load_idx(self_idx, n, is64);
    if (t < S)  sidx[t] = load_idx(neigh_idx, (size_t)n * S + t, is64);
    __syncthreads();

    uint2* Ah = reinterpret_cast<uint2*>(g_Ahi);
    uint2* Al = reinterpret_cast<uint2*>(g_Alo);

    {   // self half
        float4 v = feat4[(size_t)sidx[S] * 128 + t];
        uint2 hi, lo;
        split2(v.x, v.y, hi.x, lo.x);
        split2(v.z, v.w, hi.y, lo.y);
        Ah[(size_t)n * 256 + t] = hi;
        Al[(size_t)n * 256 + t] = lo;
    }
    float4 acc = make_float4(0.f, 0.f, 0.f, 0.f);
    for (int s = 0; s < S; ++s) {
        float4 v = feat4[(size_t)sidx[s] * 128 + t];
        acc.x += v.x; acc.y += v.y; acc.z += v.z; acc.w += v.w;
    }
    const float inv = 1.0f / (float)S;
    acc.x *= inv; acc.y *= inv; acc.z *= inv; acc.w *= inv;
    uint2 hi, lo;
    split2(acc.x, acc.y, hi.x, lo.x);
    split2(acc.z, acc.w, hi.y, lo.y);
    Ah[(size_t)n * 256 + 128 + t] = hi;
    Al[(size_t)n * 256 + 128 + t] = lo;
}

// ------------------------- kernel 1b: split W to bf16 hi/lo ----------------
__global__ __launch_bounds__(256)
void wconv_kernel(const float* __restrict__ W) {
    const int i = blockIdx.x * 256 + threadIdx.x;
    const float4 v = *(const float4*)(W + (size_t)i * 4);
    uint2 hi, lo;
    split2(v.x, v.y, hi.x, lo.x);
    split2(v.z, v.w, hi.y, lo.y);
    ((uint2*)g_Whi)[i] = hi;
    ((uint2*)g_Wlo)[i] = lo;
}

// ------------------------- kernel 2: HMMA GEMM + bias + ReLU ---------------
// H[128x128 tile] = A[128,1024] * W[128-slice,1024]^T, 3-pass hi/lo.
// smem stage: 4 variants (Ahi,Alo,Bhi,Blo) of [128 rows][32 k] bf16,
// row stride padded to 40 halfs (80B) -> conflict-free ldmatrix.
// 2 stages -> 83 KB smem -> 2 CTAs/SM.
#define SASTRIDE 80                       // bytes per smem row
#define VARB     10240                    // 128*80 bytes per variant
#define STAGEB   (4 * VARB)               // 40960
#define NSTAGE   2
#define HDRB     1024
#define GEMM_SMEM (HDRB + NSTAGE * STAGEB)

__global__ __launch_bounds__(256, 2)
void gemm_tc_kernel(const float* __restrict__ bias, int M) {
    extern __shared__ char smem[];
    const uint32_t sb = smem_u32(smem);
    const int tid  = threadIdx.x;
    const int wid  = tid >> 5;
    const int lane = tid & 31;
    const int wm   = wid >> 2;            // 0..1  (64 rows each)
    const int wn   = wid & 3;             // 0..3  (32 cols each)
    const int m0 = blockIdx.y * 128;
    const int n0 = blockIdx.x * 128;

    float* bsm = (float*)smem;            // bias cache [128]
    if (tid < 128) bsm[tid] = bias[n0 + tid];

    // per-lane ldmatrix offsets (bytes)
    const uint32_t aOff = (uint32_t)((lane & 15) * SASTRIDE + (lane >> 4) * 16);
    const uint32_t bOff = (uint32_t)(((lane & 7) + ((lane >> 4) << 3)) * SASTRIDE
                                     + (((lane >> 3) & 1) << 4));

    const char* pAhi = (const char*)g_Ahi;
    const char* pAlo = (const char*)g_Alo;
    const char* pWhi = (const char*)g_Whi;
    const char* pWlo = (const char*)g_Wlo;

    auto load_chunk = [&](int stage, int kc) {
        const uint32_t base = sb + HDRB + stage * STAGEB;
        #pragma unroll
        for (int i = 0; i < 2; ++i) {
            const int idx = tid + (i << 8);
            const int r = idx >> 2, c = idx & 3;
            const uint32_t dst = base + (uint32_t)(r * SASTRIDE + c * 16);
            const size_t sa  = ((size_t)(m0 + r) << 11) + (size_t)(kc * 64 + c * 16);
            const size_t sbo = ((size_t)(n0 + r) << 11) + (size_t)(kc * 64 + c * 16);
            cpasync16(dst,            pAhi + sa);
            cpasync16(dst + VARB,     pAlo + sa);
            cpasync16(dst + 2 * VARB, pWhi + sbo);
            cpasync16(dst + 3 * VARB, pWlo + sbo);
        }
        cp_commit();
    };

    float acc[4][4][4];
    #pragma unroll
    for (int i = 0; i < 4; ++i)
        #pragma unroll
        for (int j = 0; j < 4; ++j)
            #pragma unroll
            for (int q = 0; q < 4; ++q) acc[i][j][q] = 0.f;

    load_chunk(0, 0);
    load_chunk(1, 1);

    const int NKC = KK / 32;              // 32 chunks
    for (int kc = 0; kc < NKC; ++kc) {
        if (kc >= NKC - 2) asm volatile("cp.async.wait_group 0;" ::: "memory");
        else               asm volatile("cp.async.wait_group 1;" ::: "memory");
        __syncthreads();

        const uint32_t st = sb + HDRB + (kc & 1) * STAGEB;
        const uint32_t bufAhi = st;
        const uint32_t bufAlo = st + VARB;
        const uint32_t bufBhi = st + 2 * VARB;
        const uint32_t bufBlo = st + 3 * VARB;

        #pragma unroll
        for (int k16 = 0; k16 < 2; ++k16) {
            const uint32_t kb = (uint32_t)(k16 * 32);   // 16 halfs = 32 bytes
            uint32_t ah[4][4], al[4][4], bh[2][4], bl[2][4];
            #pragma unroll
            for (int im = 0; im < 4; ++im) {
                const uint32_t ro = (uint32_t)((wm * 64 + im * 16) * SASTRIDE) + kb;
                ldsm4(ah[im][0], ah[im][1], ah[im][2], ah[im][3], bufAhi + ro + aOff);
                ldsm4(al[im][0], al[im][1], al[im][2], al[im][3], bufAlo + ro + aOff);
            }
            #pragma unroll
            for (int j2 = 0; j2 < 2; ++j2) {
                const uint32_t ro = (uint32_t)((wn * 32 + j2 * 16) * SASTRIDE) + kb;
                ldsm4(bh[j2][0], bh[j2][1], bh[j2][2], bh[j2][3], bufBhi + ro + bOff);
                ldsm4(bl[j2][0], bl[j2][1], bl[j2][2], bl[j2][3], bufBlo + ro + bOff);
            }
            #pragma unroll
            for (int im = 0; im < 4; ++im)
                #pragma unroll
                for (int jn = 0; jn < 4; ++jn) {
                    const uint32_t* ph = &bh[jn >> 1][(jn & 1) * 2];
                    const uint32_t* pl = &bl[jn >> 1][(jn & 1) * 2];
                    mma16816(acc[im][jn], ah[im], ph);   // hi*hi
                    mma16816(acc[im][jn], ah[im], pl);   // hi*lo
                    mma16816(acc[im][jn], al[im], ph);   // lo*hi
                }
        }
        __syncthreads();
        if (kc + 2 < NKC) load_chunk(kc & 1, kc + 2);
    }

    // epilogue: bias + relu -> g_H
    const int g    = lane >> 2;
    const int tq   = lane & 3;
    #pragma unroll
    for (int im = 0; im < 4; ++im) {
        const int row0 = m0 + wm * 64 + im * 16 + g;
        #pragma unroll
        for (int jn = 0; jn < 4; ++jn) {
            const int colL = wn * 32 + jn * 8 + tq * 2;   // within 128-tile
            const float b0 = bsm[colL], b1 = bsm[colL + 1];
            float v0 = acc[im][jn][0] + b0;
            float v1 = acc[im][jn][1] + b1;
            float v2 = acc[im][jn][2] + b0;
            float v3 = acc[im][jn][3] + b1;
            v0 = v0 > 0.f ? v0 : 0.f;
            v1 = v1 > 0.f ? v1 : 0.f;
            v2 = v2 > 0.f ? v2 : 0.f;
            v3 = v3 > 0.f ? v3 : 0.f;
            const int col = n0 + colL;
            if (row0 < M)
                *(float2*)(g_H + (size_t)row0 * DD + col) = make_float2(v0, v1);
            if (row0 + 8 < M)
                *(float2*)(g_H + (size_t)(row0 + 8) * DD + col) = make_float2(v2, v3);
        }
    }
}

// ------------------------- kernel 3: BN partial stats ----------------------
__global__ __launch_bounds__(256)
void stats_kernel(int M) {
    const int b = blockIdx.x;
    const int r0 = b * 32;
    const int t = threadIdx.x;
    float s0 = 0.f, q0 = 0.f, s1 = 0.f, q1 = 0.f;
    const int rend = min(M - r0, 32);
    for (int r = 0; r < rend; ++r) {
        const float* row = g_H + (size_t)(r0 + r) * DD;
        float v = row[t];        s0 += v; q0 += v * v;
        float w = row[t + 256];  s1 += w; q1 += w * w;
    }
    g_psum  [b * DD + t]       = s0;
    g_psumsq[b * DD + t]       = q0;
    g_psum  [b * DD + t + 256] = s1;
    g_psumsq[b * DD + t + 256] = q1;
}

__global__ __launch_bounds__(256)
void finalize_stats(const float* __restrict__ gamma,
                    const float* __restrict__ beta, int M, int nblk) {
    const int col  = blockIdx.x * 8 + (threadIdx.x >> 5);
    const int lane = threadIdx.x & 31;
    float s = 0.f, q = 0.f;
    for (int i = lane; i < nblk; i += 32) {
        s += g_psum  [i * DD + col];
        q += g_psumsq[i * DD + col];
    }
    #pragma unroll
    for (int o = 16; o > 0; o >>= 1) {
        s += __shfl_xor_sync(0xffffffffu, s, o);
        q += __shfl_xor_sync(0xffffffffu, q, o);
    }
    if (lane == 0) {
        const float invM = 1.0f / (float)M;
        const float mean = s * invM;
        const float var  = q * invM - mean * mean;
        const float rstd = rsqrtf(var + 1e-5f);
        const float sc = rstd * gamma[col];
        g_scale[col] = sc;
        g_shift[col] = beta[col] - mean * sc;
    }
}

// ------------------------- kernel 4: BN apply + row L2 normalize -----------
__global__ __launch_bounds__(128)
void bn_l2_kernel(float4* __restrict__ out4, int M) {
    const int n = blockIdx.x;
    const int t = threadIdx.x;
    const float4* H4  = reinterpret_cast<const float4*>(g_H);
    const float4* sc4 = reinterpret_cast<const float4*>(g_scale);
    const float4* sh4 = reinterpret_cast<const float4*>(g_shift);

    float4 h  = H4[(size_t)n * 128 + t];
    float4 sc = sc4[t];
    float4 sh = sh4[t];
    float4 y;
    y.x = h.x * sc.x + sh.x;
    y.y = h.y * sc.y + sh.y;
    y.z = h.z * sc.z + sh.z;
    y.w = h.w * sc.w + sh.w;

    float ss = y.x * y.x + y.y * y.y + y.z * y.z + y.w * y.w;
    #pragma unroll
    for (int o = 16; o > 0; o >>= 1)
        ss += __shfl_xor_sync(0xffffffffu, ss, o);

    __shared__ float ws[4];
    if ((t & 31) == 0) ws[t >> 5] = ss;
    __syncthreads();
    const float tot = ws[0] + ws[1] + ws[2] + ws[3];
    const float inv = 1.0f / (sqrtf(tot) + 1e-6f);

    y.x *= inv; y.y *= inv; y.z *= inv; y.w *= inv;
    out4[(size_t)n * 128 + t] = y;
}

// ------------------------- launcher ----------------------------------------
extern "C" void kernel_launch(void* const* d_in, const int* in_sizes, int n_in,
                              void* d_out, int out_size) {
    const float* features = (const float*)d_in[0];
    const float* W        = (const float*)d_in[1];
    const float* b        = (const float*)d_in[2];
    const float* gamma    = (const float*)d_in[3];
    const float* beta     = (const float*)d_in[4];
    const void*  self_idx = d_in[5];
    const void*  neigh_idx= d_in[6];

    const int N = in_sizes[5];
    const int S = in_sizes[6] / N;

    cudaFuncSetAttribute(gemm_tc_kernel,
                         cudaFuncAttributeMaxDynamicSharedMemorySize, GEMM_SMEM);

    detect_idx_kernel<<<1, 256>>>((const unsigned int*)self_idx, N);

    agg_kernel<<<N, 128>>>((const float4*)features, self_idx, neigh_idx, N, S);
    wconv_kernel<<<(DD * KK / 4) / 256, 256>>>(W);

    dim3 ggrid(DD / 128, (N + 127) / 128);
    gemm_tc_kernel<<<ggrid, 256, GEMM_SMEM>>>(b, N);

    const int nblk = (N + 31) / 32;
    stats_kernel<<<nblk, 256>>>(N);
    finalize_stats<<<64, 256>>>(gamma, beta, N, nblk);

    bn_l2_kernel<<<N, 128>>>((float4*)d_out, N);
}